// round 1
// baseline (speedup 1.0000x reference)
#include <cuda_runtime.h>

#define CIN   128
#define COUT  128
#define KHW   9
#define NB    (CIN*COUT*KHW)   // 147456
#define ZD    256
#define BATCH 32
#define HW    32
#define HW2   (HW*HW)          // 1024

// Scratch: per-sample normalized kernels, layout (b, s, f, uv) contiguous
__device__ float g_Wk[BATCH * NB];   // 18.9 MB

// ---------------------------------------------------------------------------
// Kernel A: h = relu(z @ dense_w + dense_b); BN over batch axis; gamma/beta.
// One thread owns one unit j: all 32 batch values live in registers, so the
// batch-norm fuses into the epilogue with zero extra memory passes.
// ---------------------------------------------------------------------------
__global__ __launch_bounds__(256) void hyper_kernel(
    const float* __restrict__ z,      // (32,256)
    const float* __restrict__ dw,     // (256, NB)
    const float* __restrict__ db,     // (NB)
    const float* __restrict__ gamma,  // (NB)
    const float* __restrict__ beta)   // (NB)
{
    __shared__ float zs[BATCH * ZD];
    const int tid = threadIdx.x;
    for (int i = tid; i < BATCH * ZD; i += 256) zs[i] = z[i];
    __syncthreads();

    const int j = blockIdx.x * 256 + tid;

    float acc[BATCH];
    const float bias = db[j];
#pragma unroll
    for (int b = 0; b < BATCH; b++) acc[b] = bias;

    for (int k = 0; k < ZD; k += 4) {
        const float w0 = dw[(k + 0) * NB + j];
        const float w1 = dw[(k + 1) * NB + j];
        const float w2 = dw[(k + 2) * NB + j];
        const float w3 = dw[(k + 3) * NB + j];
#pragma unroll
        for (int b = 0; b < BATCH; b++) {
            float4 z4 = *reinterpret_cast<const float4*>(&zs[b * ZD + k]);
            acc[b] = fmaf(z4.x, w0, acc[b]);
            acc[b] = fmaf(z4.y, w1, acc[b]);
            acc[b] = fmaf(z4.z, w2, acc[b]);
            acc[b] = fmaf(z4.w, w3, acc[b]);
        }
    }

    // relu
#pragma unroll
    for (int b = 0; b < BATCH; b++) acc[b] = fmaxf(acc[b], 0.0f);

    // batch stats (two-pass, exact-ish)
    float mean = 0.0f;
#pragma unroll
    for (int b = 0; b < BATCH; b++) mean += acc[b];
    mean *= (1.0f / BATCH);
    float var = 0.0f;
#pragma unroll
    for (int b = 0; b < BATCH; b++) { float d = acc[b] - mean; var = fmaf(d, d, var); }
    var *= (1.0f / BATCH);

    const float scale = gamma[j] / (sqrtf(var) + 1e-6f);
    const float bet   = beta[j];

#pragma unroll
    for (int b = 0; b < BATCH; b++)
        g_Wk[b * NB + j] = (acc[b] - mean) * scale + bet;
}

// ---------------------------------------------------------------------------
// Kernel B: per-sample conv (pad 1) + bias + residual.
// GEMM view per sample: out[f, px] = sum_{s,uv} W[b][s,f,uv] * patch[s,uv, px]
// CTA: one sample b, all 128 f, 128 pixels (4 image rows). K-loop over
// channel chunks of 8 (72 k-values). Thread tile 8f x 8px.
// ---------------------------------------------------------------------------
#define SCH    8                 // channels per K-chunk
#define WPITCH 132               // smem pitch for W rows (128 + pad)
#define XPITCH 36                // smem pitch for x rows (34 + pad)

__global__ __launch_bounds__(256, 2) void conv_kernel(
    const float* __restrict__ x,     // (32,128,32,32)
    const float* __restrict__ bias,  // (128)
    float* __restrict__ out)         // (32,128,32,32)
{
    __shared__ float Wsm[SCH * KHW * WPITCH];   // 72 x 132 floats
    __shared__ float xs[SCH * 6 * XPITCH];      // 8 ch x 6 rows x 36 cols

    const int b     = blockIdx.y;
    const int p0    = blockIdx.x * 4;           // first output row of tile
    const int tid   = threadIdx.x;
    const int tx    = tid & 15;                 // pixel group (8 px each)
    const int ty    = tid >> 4;                 // f group (8 f each)
    const int px0   = tx * 8;
    const int rloc  = px0 >> 5;                 // row within 4-row tile
    const int c0    = px0 & 31;                 // starting column
    const int f0    = ty * 8;

    float acc[8][8];
#pragma unroll
    for (int i = 0; i < 8; i++)
#pragma unroll
        for (int jj = 0; jj < 8; jj++) acc[i][jj] = 0.0f;

    const float* Wg = g_Wk + b * NB;
    const float* xg = x + b * CIN * HW2;

    for (int s0 = 0; s0 < CIN; s0 += SCH) {
        __syncthreads();

        // --- load W chunk: SCH*COUT*KHW = 9216 floats, contiguous in gmem ---
        {
            const float4* wsrc = reinterpret_cast<const float4*>(Wg + s0 * (COUT * KHW));
            for (int t4 = tid; t4 < (SCH * COUT * KHW) / 4; t4 += 256) {
                float4 v = wsrc[t4];
                int base = t4 * 4;
#pragma unroll
                for (int e = 0; e < 4; e++) {
                    int t  = base + e;
                    int sc = t / (COUT * KHW);
                    int r  = t - sc * (COUT * KHW);
                    int f  = r / KHW;
                    int uv = r - f * KHW;
                    Wsm[(sc * KHW + uv) * WPITCH + f] = (&v.x)[e];
                }
            }
        }

        // --- load x tile with halo: SCH ch, rows p0-1..p0+4, cols -1..32 ---
        for (int t = tid; t < SCH * 6 * 34; t += 256) {
            int sc = t / (6 * 34);
            int r2 = t - sc * (6 * 34);
            int rr = r2 / 34;
            int cc = r2 - rr * 34;
            int gp = p0 - 1 + rr;
            int gq = cc - 1;
            float v = 0.0f;
            if (gp >= 0 && gp < HW && gq >= 0 && gq < HW)
                v = xg[(s0 + sc) * HW2 + gp * HW + gq];
            xs[(sc * 6 + rr) * XPITCH + cc] = v;
        }
        __syncthreads();

        // --- compute ---
#pragma unroll
        for (int sc = 0; sc < SCH; sc++) {
#pragma unroll
            for (int u = 0; u < 3; u++) {
                // 12 x-floats covering cols c0..c0+11 of shifted row
                float xr[12];
                const float* xrow = &xs[(sc * 6 + rloc + u) * XPITCH + c0];
                *reinterpret_cast<float4*>(&xr[0]) = *reinterpret_cast<const float4*>(&xrow[0]);
                *reinterpret_cast<float4*>(&xr[4]) = *reinterpret_cast<const float4*>(&xrow[4]);
                *reinterpret_cast<float4*>(&xr[8]) = *reinterpret_cast<const float4*>(&xrow[8]);
#pragma unroll
                for (int v = 0; v < 3; v++) {
                    float w[8];
                    const float* wrow = &Wsm[(sc * KHW + u * 3 + v) * WPITCH + f0];
                    *reinterpret_cast<float4*>(&w[0]) = *reinterpret_cast<const float4*>(&wrow[0]);
                    *reinterpret_cast<float4*>(&w[4]) = *reinterpret_cast<const float4*>(&wrow[4]);
#pragma unroll
                    for (int i = 0; i < 8; i++)
#pragma unroll
                        for (int jj = 0; jj < 8; jj++)
                            acc[i][jj] = fmaf(w[i], xr[jj + v], acc[i][jj]);
                }
            }
        }
    }

    // --- epilogue: + bias + residual x ---
#pragma unroll
    for (int i = 0; i < 8; i++) {
        const int f  = f0 + i;
        const float bv = bias[f];
        const int idx = f * HW2 + p0 * HW + px0;   // within sample
#pragma unroll
        for (int jj = 0; jj < 8; jj++) {
            out[b * CIN * HW2 + idx + jj] = acc[i][jj] + xg[idx + jj] + bv;
        }
    }
}

// ---------------------------------------------------------------------------
extern "C" void kernel_launch(void* const* d_in, const int* in_sizes, int n_in,
                              void* d_out, int out_size)
{
    const float* x     = (const float*)d_in[0];
    const float* z     = (const float*)d_in[1];
    const float* dw    = (const float*)d_in[2];
    const float* db    = (const float*)d_in[3];
    const float* gamma = (const float*)d_in[4];
    const float* beta  = (const float*)d_in[5];
    const float* bconv = (const float*)d_in[6];
    float* out = (float*)d_out;

    hyper_kernel<<<NB / 256, 256>>>(z, dw, db, gamma, beta);
    conv_kernel<<<dim3(8, BATCH), 256>>>(x, bconv, out);
}

// round 4
// speedup vs baseline: 1.5974x; 1.5974x over previous
#include <cuda_runtime.h>
#include <cuda_bf16.h>
#include <cstdint>

#define CIN   128
#define COUT  128
#define KHW   9
#define NB    (CIN*COUT*KHW)   // 147456
#define ZD    256
#define BATCH 32
#define HW    32
#define HW2   (HW*HW)

// ---------------- scratch (device globals; no allocs allowed) ----------------
__device__ __align__(1024) float          g_Wk[BATCH * NB];                 // fp32 (b,s,f,uv)
__device__ __align__(1024) __nv_bfloat16  g_W2hi[BATCH * 9 * 128 * 128];    // (b,uv,f,s)
__device__ __align__(1024) __nv_bfloat16  g_W2lo[BATCH * 9 * 128 * 128];
__device__ __align__(1024) __nv_bfloat16  g_xhi[BATCH * 34 * 36 * 128];     // (b,row,col,s) padded, pad stays 0
__device__ __align__(1024) __nv_bfloat16  g_xlo[BATCH * 34 * 36 * 128];

// ---------------- helpers ----------------
__device__ __forceinline__ uint32_t smem_u32(const void* p) {
    uint32_t a;
    asm("{ .reg .u64 t; cvta.to.shared.u64 t, %1; cvt.u32.u64 %0, t; }" : "=r"(a) : "l"(p));
    return a;
}
__device__ __forceinline__ void cp16(uint32_t dst, const void* src) {
    asm volatile("cp.async.cg.shared.global [%0], [%1], 16;" :: "r"(dst), "l"(src) : "memory");
}
#define CP_COMMIT() asm volatile("cp.async.commit_group;" ::: "memory")

__device__ __forceinline__ void ldsm4(uint32_t* r, uint32_t a) {
    asm volatile("ldmatrix.sync.aligned.m8n8.x4.shared.b16 {%0,%1,%2,%3}, [%4];"
                 : "=r"(r[0]), "=r"(r[1]), "=r"(r[2]), "=r"(r[3]) : "r"(a));
}
__device__ __forceinline__ void mma16816(float* d, const uint32_t* a, const uint32_t* b) {
    asm volatile(
        "mma.sync.aligned.m16n8k16.row.col.f32.bf16.bf16.f32 "
        "{%0,%1,%2,%3}, {%4,%5,%6,%7}, {%8,%9}, {%0,%1,%2,%3};"
        : "+f"(d[0]), "+f"(d[1]), "+f"(d[2]), "+f"(d[3])
        : "r"(a[0]), "r"(a[1]), "r"(a[2]), "r"(a[3]), "r"(b[0]), "r"(b[1]));
}

// ===========================================================================
// Kernel A: hypernetwork GEMM + fused BN (proven R1 version)
// ===========================================================================
__global__ __launch_bounds__(256) void hyper_kernel(
    const float* __restrict__ z, const float* __restrict__ dw,
    const float* __restrict__ db, const float* __restrict__ gamma,
    const float* __restrict__ beta)
{
    __shared__ float zs[BATCH * ZD];
    const int tid = threadIdx.x;
    for (int i = tid; i < BATCH * ZD; i += 256) zs[i] = z[i];
    __syncthreads();

    const int j = blockIdx.x * 256 + tid;
    float acc[BATCH];
    const float bias = db[j];
#pragma unroll
    for (int b = 0; b < BATCH; b++) acc[b] = bias;

    for (int k = 0; k < ZD; k += 4) {
        const float w0 = dw[(k + 0) * NB + j];
        const float w1 = dw[(k + 1) * NB + j];
        const float w2 = dw[(k + 2) * NB + j];
        const float w3 = dw[(k + 3) * NB + j];
#pragma unroll
        for (int b = 0; b < BATCH; b++) {
            float4 z4 = *reinterpret_cast<const float4*>(&zs[b * ZD + k]);
            acc[b] = fmaf(z4.x, w0, acc[b]);
            acc[b] = fmaf(z4.y, w1, acc[b]);
            acc[b] = fmaf(z4.z, w2, acc[b]);
            acc[b] = fmaf(z4.w, w3, acc[b]);
        }
    }
#pragma unroll
    for (int b = 0; b < BATCH; b++) acc[b] = fmaxf(acc[b], 0.0f);

    float mean = 0.0f;
#pragma unroll
    for (int b = 0; b < BATCH; b++) mean += acc[b];
    mean *= (1.0f / BATCH);
    float var = 0.0f;
#pragma unroll
    for (int b = 0; b < BATCH; b++) { float d = acc[b] - mean; var = fmaf(d, d, var); }
    var *= (1.0f / BATCH);

    const float scale = gamma[j] / (sqrtf(var) + 1e-6f);
    const float bet = beta[j];
#pragma unroll
    for (int b = 0; b < BATCH; b++)
        g_Wk[b * NB + j] = (acc[b] - mean) * scale + bet;
}

// ===========================================================================
// Kernel W: transpose + bf16-split W: (b,s,f,uv) fp32 -> (b,uv,f,s) hi/lo
// ===========================================================================
__global__ __launch_bounds__(256) void wtrans_kernel()
{
    __shared__ float sWk[9224];  // pitch 1153 per s_local
    const int b = blockIdx.y, sblk = blockIdx.x, tid = threadIdx.x;
    const float* src = g_Wk + (size_t)b * NB + (size_t)sblk * 9216;
    for (int i = tid; i < 9216; i += 256) {
        int sl = i / 1152;
        sWk[i + sl] = src[i];
    }
    __syncthreads();
    for (int t = tid; t < 9216; t += 256) {
        int uv = t >> 10, f = (t >> 3) & 127, sl = t & 7;
        float v = sWk[sl * 1153 + f * 9 + uv];
        __nv_bfloat16 h = __float2bfloat16(v);
        __nv_bfloat16 l = __float2bfloat16(v - __bfloat162float(h));
        size_t o = (((size_t)(b * 9 + uv) * 128) + f) * 128 + sblk * 8 + sl;
        g_W2hi[o] = h;
        g_W2lo[o] = l;
    }
}

// ===========================================================================
// Kernel X: x -> padded channel-last split-bf16 (b, row 34, col 36, s 128)
// ===========================================================================
__global__ __launch_bounds__(256) void xprep_kernel(const float* __restrict__ x)
{
    __shared__ float sX[128 * 33];
    const int b = blockIdx.y, p = blockIdx.x, tid = threadIdx.x;
    for (int i = tid; i < 4096; i += 256) {
        int s = i >> 5, q = i & 31;
        sX[s * 33 + q] = x[(((size_t)(b * 128 + s)) * 32 + p) * 32 + q];
    }
    __syncthreads();
    for (int i = tid; i < 4096; i += 256) {
        int s = i & 127, q = i >> 7;
        float v = sX[s * 33 + q];
        __nv_bfloat16 h = __float2bfloat16(v);
        __nv_bfloat16 l = __float2bfloat16(v - __bfloat162float(h));
        size_t o = (((size_t)b * 34 + (p + 1)) * 36 + (q + 1)) * 128 + s;
        g_xhi[o] = h;
        g_xlo[o] = l;
    }
}

// ===========================================================================
// Kernel C: per-sample conv as split-bf16 HMMA GEMM.
// CTA: sample b x pixel-block (256 px = 8 image rows). M=128(f), N=256(px).
// 512 threads, 16 warps, warp tile 32f x 64px. K = 9uv x 128s, staged as
// 18 chunks of (uv, 64s), double-buffered via cp.async.
// Split-bf16: acc += Ah*Bh + Ah*Bl + Al*Bh  (ll term ~2^-18, dropped).
// B fragments: smem [n][k] + NON-trans ldmatrix == .row.col B operand.
// ===========================================================================
// per-buffer layout (bytes): Ah@0 18432 | Al@18432 | Bh@36864 36864 | Bl@73728
#define APITCH 144           // 64 bf16 + 8 pad
#define BUFSZ  110592
#define CSMEM  221184

__global__ __launch_bounds__(512, 1) void conv_mma_kernel(
    const float* __restrict__ xin,
    const float* __restrict__ bias,
    float* __restrict__ out)
{
    extern __shared__ char smem[];
    const uint32_t sb = smem_u32(smem);
    const int tid = threadIdx.x, wid = tid >> 5, lane = tid & 31;
    const int b = blockIdx.y, pb = blockIdx.x;   // pixel rows pb*8 .. pb*8+7
    const int f0 = (wid >> 2) * 32;
    const int px0 = (wid & 3) * 64;

    float d[2][8][4];
#pragma unroll
    for (int i = 0; i < 2; i++)
#pragma unroll
        for (int j = 0; j < 8; j++)
#pragma unroll
            for (int e = 0; e < 4; e++) d[i][j][e] = 0.0f;

    // loop-invariant ldmatrix lane offsets
    const uint32_t aoff = (uint32_t)((lane & 15) * APITCH + (lane >> 4) * 16);
    const uint32_t boff = (uint32_t)(((lane & 7) + ((lane >> 4) << 3)) * APITCH + ((lane >> 3) & 1) * 16);

    // ---- stage loader ----
    auto issue_stage = [&](int st) {
        const int uv = st >> 1, c = st & 1;
        const int u = uv / 3, v = uv - 3 * u;
        const uint32_t base = sb + (uint32_t)(st & 1) * BUFSZ;
        // A: 2048 16B chunks (128 f-rows x 8 segs x 2 halves)
#pragma unroll
        for (int i = 0; i < 4; i++) {
            int c2 = i * 512 + tid;
            int half = c2 >> 10, rem = c2 & 1023, row = rem >> 3, seg = rem & 7;
            const __nv_bfloat16* src =
                (half ? g_W2lo : g_W2hi) +
                (((size_t)(b * 9 + uv) * 128 + row) * 128 + c * 64 + seg * 8);
            cp16(base + half * 18432 + row * APITCH + seg * 16, src);
        }
        // B: 4096 16B chunks (256 px-rows x 8 segs x 2 halves)
#pragma unroll
        for (int i = 0; i < 8; i++) {
            int c2 = i * 512 + tid;
            int half = c2 >> 11, rem = c2 & 2047, px = rem >> 3, seg = rem & 7;
            int prow = pb * 8 + (px >> 5), pcol = px & 31;
            const __nv_bfloat16* src =
                (half ? g_xlo : g_xhi) +
                (((size_t)(b * 34 + prow + u) * 36 + (pcol + v)) * 128 + c * 64 + seg * 8);
            cp16(base + 36864 + half * 36864 + px * APITCH + seg * 16, src);
        }
        CP_COMMIT();
    };

    issue_stage(0);
    issue_stage(1);

    for (int st = 0; st < 18; st++) {
        if (st < 17) asm volatile("cp.async.wait_group 1;" ::: "memory");
        else         asm volatile("cp.async.wait_group 0;" ::: "memory");
        __syncthreads();

        const uint32_t base = sb + (uint32_t)(st & 1) * BUFSZ;
        const uint32_t baseAh = base, baseAl = base + 18432;
        const uint32_t baseBh = base + 36864, baseBl = base + 73728;

#pragma unroll
        for (int kk = 0; kk < 4; kk++) {
            const uint32_t ko = (uint32_t)kk * 32;
            uint32_t ah[2][4], al[2][4], bf[4][4];
#pragma unroll
            for (int i = 0; i < 2; i++) {
                ldsm4(ah[i], baseAh + (f0 + i * 16) * APITCH + ko + aoff);
                ldsm4(al[i], baseAl + (f0 + i * 16) * APITCH + ko + aoff);
            }
#pragma unroll
            for (int p = 0; p < 4; p++)
                ldsm4(bf[p], baseBh + (px0 + p * 16) * APITCH + ko + boff);
            // hh + lh
#pragma unroll
            for (int i = 0; i < 2; i++)
#pragma unroll
                for (int t = 0; t < 8; t++)
                    mma16816(d[i][t], ah[i], &bf[t >> 1][(t & 1) * 2]);
#pragma unroll
            for (int i = 0; i < 2; i++)
#pragma unroll
                for (int t = 0; t < 8; t++)
                    mma16816(d[i][t], al[i], &bf[t >> 1][(t & 1) * 2]);
            // hl (reload B-low into same regs)
#pragma unroll
            for (int p = 0; p < 4; p++)
                ldsm4(bf[p], baseBl + (px0 + p * 16) * APITCH + ko + boff);
#pragma unroll
            for (int i = 0; i < 2; i++)
#pragma unroll
                for (int t = 0; t < 8; t++)
                    mma16816(d[i][t], ah[i], &bf[t >> 1][(t & 1) * 2]);
        }
        __syncthreads();
        if (st + 2 < 18) issue_stage(st + 2);
    }

    // ---- epilogue: + residual + bias, direct fragment stores ----
    const int g = lane >> 2, tc = lane & 3;
#pragma unroll
    for (int i = 0; i < 2; i++) {
        const int fr0 = f0 + i * 16 + g;
        const float bv0 = __ldg(&bias[fr0]);
        const float bv1 = __ldg(&bias[fr0 + 8]);
#pragma unroll
        for (int j = 0; j < 8; j++) {
            const int pix = pb * 256 + px0 + j * 8 + tc * 2;
            {
                size_t o = ((size_t)(b * 128 + fr0)) * 1024 + pix;
                float2 xr = *reinterpret_cast<const float2*>(xin + o);
                float2 w = make_float2(d[i][j][0] + xr.x + bv0,
                                       d[i][j][1] + xr.y + bv0);
                *reinterpret_cast<float2*>(out + o) = w;
            }
            {
                size_t o = ((size_t)(b * 128 + fr0 + 8)) * 1024 + pix;
                float2 xr = *reinterpret_cast<const float2*>(xin + o);
                float2 w = make_float2(d[i][j][2] + xr.x + bv1,
                                       d[i][j][3] + xr.y + bv1);
                *reinterpret_cast<float2*>(out + o) = w;
            }
        }
    }
}

// ===========================================================================
extern "C" void kernel_launch(void* const* d_in, const int* in_sizes, int n_in,
                              void* d_out, int out_size)
{
    (void)in_sizes; (void)n_in; (void)out_size;
    const float* x     = (const float*)d_in[0];
    const float* z     = (const float*)d_in[1];
    const float* dw    = (const float*)d_in[2];
    const float* db    = (const float*)d_in[3];
    const float* gamma = (const float*)d_in[4];
    const float* beta  = (const float*)d_in[5];
    const float* bconv = (const float*)d_in[6];
    float* out = (float*)d_out;

    cudaFuncSetAttribute(conv_mma_kernel,
                         cudaFuncAttributeMaxDynamicSharedMemorySize, CSMEM);

    hyper_kernel<<<NB / 256, 256>>>(z, dw, db, gamma, beta);
    xprep_kernel<<<dim3(32, BATCH), 256>>>(x);
    wtrans_kernel<<<dim3(16, BATCH), 256>>>();
    conv_mma_kernel<<<dim3(4, BATCH), 512, CSMEM>>>(x, bconv, out);
}

// round 5
// speedup vs baseline: 2.2863x; 1.4312x over previous
#include <cuda_runtime.h>
#include <cuda_bf16.h>
#include <cstdint>

#define CIN   128
#define COUT  128
#define KHW   9
#define NB    (CIN*COUT*KHW)   // 147456
#define ZD    256
#define BATCH 32
#define HW    32
#define HW2   (HW*HW)

// ---------------- scratch (device globals; no allocs allowed) ----------------
__device__ __align__(1024) float          g_Wk[BATCH * NB];                 // fp32 (b,s,f,uv)
__device__ __align__(1024) __nv_bfloat16  g_W2hi[BATCH * 9 * 128 * 128];    // (b,uv,f,s)
__device__ __align__(1024) __nv_bfloat16  g_W2lo[BATCH * 9 * 128 * 128];
__device__ __align__(1024) __nv_bfloat16  g_xhi[BATCH * 34 * 36 * 128];     // (b,row,col,s) padded, pad stays 0
__device__ __align__(1024) __nv_bfloat16  g_xlo[BATCH * 34 * 36 * 128];

// ---------------- helpers ----------------
__device__ __forceinline__ uint32_t smem_u32(const void* p) {
    uint32_t a;
    asm("{ .reg .u64 t; cvta.to.shared.u64 t, %1; cvt.u32.u64 %0, t; }" : "=r"(a) : "l"(p));
    return a;
}
__device__ __forceinline__ void cp16(uint32_t dst, const void* src) {
    asm volatile("cp.async.cg.shared.global [%0], [%1], 16;" :: "r"(dst), "l"(src) : "memory");
}
#define CP_COMMIT() asm volatile("cp.async.commit_group;" ::: "memory")

__device__ __forceinline__ void ldsm4(uint32_t* r, uint32_t a) {
    asm volatile("ldmatrix.sync.aligned.m8n8.x4.shared.b16 {%0,%1,%2,%3}, [%4];"
                 : "=r"(r[0]), "=r"(r[1]), "=r"(r[2]), "=r"(r[3]) : "r"(a));
}
__device__ __forceinline__ void ldsm4t(uint32_t* r, uint32_t a) {
    asm volatile("ldmatrix.sync.aligned.m8n8.x4.trans.shared.b16 {%0,%1,%2,%3}, [%4];"
                 : "=r"(r[0]), "=r"(r[1]), "=r"(r[2]), "=r"(r[3]) : "r"(a));
}
__device__ __forceinline__ void mma16816(float* d, const uint32_t* a, const uint32_t* b) {
    asm volatile(
        "mma.sync.aligned.m16n8k16.row.col.f32.bf16.bf16.f32 "
        "{%0,%1,%2,%3}, {%4,%5,%6,%7}, {%8,%9}, {%0,%1,%2,%3};"
        : "+f"(d[0]), "+f"(d[1]), "+f"(d[2]), "+f"(d[3])
        : "r"(a[0]), "r"(a[1]), "r"(a[2]), "r"(a[3]), "r"(b[0]), "r"(b[1]));
}
__device__ __forceinline__ uint32_t pack_hi(float a, float b) {
    __nv_bfloat162 p = __floats2bfloat162_rn(a, b);
    return *reinterpret_cast<uint32_t*>(&p);
}
__device__ __forceinline__ uint32_t pack_lo(float a, float b, uint32_t hi) {
    __nv_bfloat162 h = *reinterpret_cast<__nv_bfloat162*>(&hi);
    __nv_bfloat162 p = __floats2bfloat162_rn(a - __bfloat162float(h.x),
                                             b - __bfloat162float(h.y));
    return *reinterpret_cast<uint32_t*>(&p);
}

// ===========================================================================
// Kernel A: hypernetwork GEMM on tensor cores with fused fp32->split-bf16
// conversion of dense_w and fused BatchNorm epilogue.
//   M=32 (batch), K=256, N tile = 256 per CTA (576 CTAs).
//   dw staged fp32 via cp.async (dbl buffer), converted to bf16 hi/lo smem,
//   B frags via ldmatrix.trans on [k][n]; A (z) resident split-bf16.
//   3-term split product: AhBh + AhBl + AlBh.
// smem byte layout (relative):
//   A_HI 0 (16896) | A_LO 16896 | F32 33792 (2 x 33280) | BH 100352 | BL 117248
// ===========================================================================
#define HP_PITCH 528
#define HP_F32P  1040
#define HP_RAHI  0
#define HP_RALO  16896
#define HP_RF32  33792
#define HP_RBH   100352
#define HP_RBL   117248
#define HP_SMEM  134144

__global__ __launch_bounds__(512, 1) void hyper_mma_kernel(
    const float* __restrict__ z, const float* __restrict__ dw,
    const float* __restrict__ db, const float* __restrict__ gamma,
    const float* __restrict__ beta)
{
    extern __shared__ char hs[];
    const uint32_t sb = smem_u32(hs);
    const int tid = threadIdx.x, wid = tid >> 5, lane = tid & 31;
    const int n0 = blockIdx.x * 256;
    const int wn0 = wid * 16;

    auto issue = [&](int s) {
#pragma unroll
        for (int i = 0; i < 4; i++) {
            int chunk = tid + i * 512;
            int k = chunk >> 6, seg = chunk & 63;
            cp16(sb + HP_RF32 + (s & 1) * 33280 + k * HP_F32P + seg * 16,
                 dw + (size_t)(s * 32 + k) * NB + n0 + seg * 4);
        }
        CP_COMMIT();
    };
    issue(0); CP_COMMIT();  // keep group boundaries: issue() already commits
    issue(1);

    // A (z) -> split bf16 smem [m=32][k=256], pitch 528B
    {
        const int m = tid >> 4, k0 = (tid & 15) * 16;
        const float4* zsrc = reinterpret_cast<const float4*>(z + m * ZD + k0);
        char* rowh = hs + HP_RAHI + m * HP_PITCH + k0 * 2;
        char* rowl = hs + HP_RALO + m * HP_PITCH + k0 * 2;
#pragma unroll
        for (int j = 0; j < 4; j++) {
            float4 v = zsrc[j];
            uint32_t h01 = pack_hi(v.x, v.y), h23 = pack_hi(v.z, v.w);
            uint32_t l01 = pack_lo(v.x, v.y, h01), l23 = pack_lo(v.z, v.w, h23);
            *reinterpret_cast<uint2*>(rowh + j * 8) = make_uint2(h01, h23);
            *reinterpret_cast<uint2*>(rowl + j * 8) = make_uint2(l01, l23);
        }
    }

    float d[2][2][4];
#pragma unroll
    for (int mt = 0; mt < 2; mt++)
#pragma unroll
        for (int nt = 0; nt < 2; nt++)
#pragma unroll
            for (int e = 0; e < 4; e++) d[mt][nt][e] = 0.0f;

    const uint32_t aoff = (uint32_t)((lane & 15) * HP_PITCH + (lane >> 4) * 16);
    const uint32_t boff = (uint32_t)((((lane >> 3) & 1) * 8 + (lane & 7)) * HP_PITCH
                                     + (wn0 + (lane >> 4) * 8) * 2);

    for (int s = 0; s < 8; s++) {
        if (s < 6) asm volatile("cp.async.wait_group 1;" ::: "memory");
        else       asm volatile("cp.async.wait_group 0;" ::: "memory");
        __syncthreads();

        // convert fp32 chunk [32k x 256n] -> BH/BL [k][n] bf16
        {
            const int k = tid >> 4;
            const float* frow = reinterpret_cast<const float*>(
                hs + HP_RF32 + (s & 1) * 33280 + k * HP_F32P);
            char* bh = hs + HP_RBH + k * HP_PITCH;
            char* bl = hs + HP_RBL + k * HP_PITCH;
#pragma unroll
            for (int j = 0; j < 4; j++) {
                int n4 = (tid & 15) * 4 + j * 64;
                float4 v = *reinterpret_cast<const float4*>(frow + n4);
                uint32_t h01 = pack_hi(v.x, v.y), h23 = pack_hi(v.z, v.w);
                uint32_t l01 = pack_lo(v.x, v.y, h01), l23 = pack_lo(v.z, v.w, h23);
                *reinterpret_cast<uint2*>(bh + n4 * 2) = make_uint2(h01, h23);
                *reinterpret_cast<uint2*>(bl + n4 * 2) = make_uint2(l01, l23);
            }
        }
        __syncthreads();
        if (s + 2 < 8) issue(s + 2);

#pragma unroll
        for (int kk = 0; kk < 2; kk++) {
            uint32_t ah[2][4], al[2][4], bh[4], bl[4];
            const uint32_t akoff = (uint32_t)(s * 64 + kk * 32);
#pragma unroll
            for (int mt = 0; mt < 2; mt++) {
                ldsm4(ah[mt], sb + HP_RAHI + mt * 16 * HP_PITCH + akoff + aoff);
                ldsm4(al[mt], sb + HP_RALO + mt * 16 * HP_PITCH + akoff + aoff);
            }
            ldsm4t(bh, sb + HP_RBH + kk * 16 * HP_PITCH + boff);
            ldsm4t(bl, sb + HP_RBL + kk * 16 * HP_PITCH + boff);
#pragma unroll
            for (int mt = 0; mt < 2; mt++)
#pragma unroll
                for (int nt = 0; nt < 2; nt++) {
                    mma16816(d[mt][nt], ah[mt], &bh[nt * 2]);
                    mma16816(d[mt][nt], ah[mt], &bl[nt * 2]);
                    mma16816(d[mt][nt], al[mt], &bh[nt * 2]);
                }
        }
    }

    // ---- epilogue: relu + BN over the 32 batch rows (warp-local) ----
    const int jc = n0 + wn0 + 2 * (lane & 3);
    float2 db2[2], g2[2], bt2[2];
#pragma unroll
    for (int nt = 0; nt < 2; nt++) {
        db2[nt] = *reinterpret_cast<const float2*>(db + jc + nt * 8);
        g2[nt]  = *reinterpret_cast<const float2*>(gamma + jc + nt * 8);
        bt2[nt] = *reinterpret_cast<const float2*>(beta + jc + nt * 8);
    }
#pragma unroll
    for (int mt = 0; mt < 2; mt++)
#pragma unroll
        for (int nt = 0; nt < 2; nt++) {
            d[mt][nt][0] = fmaxf(d[mt][nt][0] + db2[nt].x, 0.0f);
            d[mt][nt][1] = fmaxf(d[mt][nt][1] + db2[nt].y, 0.0f);
            d[mt][nt][2] = fmaxf(d[mt][nt][2] + db2[nt].x, 0.0f);
            d[mt][nt][3] = fmaxf(d[mt][nt][3] + db2[nt].y, 0.0f);
        }

    float sm[2][2], sq[2][2];
#pragma unroll
    for (int nt = 0; nt < 2; nt++)
#pragma unroll
        for (int c = 0; c < 2; c++) {
            float s1 = d[0][nt][c] + d[0][nt][c + 2] + d[1][nt][c] + d[1][nt][c + 2];
            float q1 = d[0][nt][c] * d[0][nt][c] + d[0][nt][c + 2] * d[0][nt][c + 2]
                     + d[1][nt][c] * d[1][nt][c] + d[1][nt][c + 2] * d[1][nt][c + 2];
#pragma unroll
            for (int o = 4; o < 32; o <<= 1) {
                s1 += __shfl_xor_sync(0xffffffffu, s1, o);
                q1 += __shfl_xor_sync(0xffffffffu, q1, o);
            }
            sm[nt][c] = s1 * (1.0f / 32.0f);
            float var = fmaxf(q1 * (1.0f / 32.0f) - sm[nt][c] * sm[nt][c], 0.0f);
            float gm = (c == 0) ? ((nt == 0) ? g2[0].x : g2[1].x)
                                : ((nt == 0) ? g2[0].y : g2[1].y);
            sq[nt][c] = gm / (sqrtf(var) + 1e-6f);
        }

    const int g = lane >> 2;
#pragma unroll
    for (int mt = 0; mt < 2; mt++)
#pragma unroll
        for (int nt = 0; nt < 2; nt++) {
            const int j = jc + nt * 8;
            float2 o0 = make_float2((d[mt][nt][0] - sm[nt][0]) * sq[nt][0] + bt2[nt].x,
                                    (d[mt][nt][1] - sm[nt][1]) * sq[nt][1] + bt2[nt].y);
            float2 o1 = make_float2((d[mt][nt][2] - sm[nt][0]) * sq[nt][0] + bt2[nt].x,
                                    (d[mt][nt][3] - sm[nt][1]) * sq[nt][1] + bt2[nt].y);
            *reinterpret_cast<float2*>(g_Wk + (size_t)(mt * 16 + g) * NB + j) = o0;
            *reinterpret_cast<float2*>(g_Wk + (size_t)(mt * 16 + g + 8) * NB + j) = o1;
        }
}

// ===========================================================================
// Kernel W: transpose + bf16-split W: (b,s,f,uv) fp32 -> (b,uv,f,s) hi/lo
// ===========================================================================
__global__ __launch_bounds__(256) void wtrans_kernel()
{
    __shared__ float sWk[9224];  // pitch 1153 per s_local
    const int b = blockIdx.y, sblk = blockIdx.x, tid = threadIdx.x;
    const float* src = g_Wk + (size_t)b * NB + (size_t)sblk * 9216;
    for (int i = tid; i < 9216; i += 256) {
        int sl = i / 1152;
        sWk[i + sl] = src[i];
    }
    __syncthreads();
    for (int t = tid; t < 9216; t += 256) {
        int uv = t >> 10, f = (t >> 3) & 127, sl = t & 7;
        float v = sWk[sl * 1153 + f * 9 + uv];
        __nv_bfloat16 h = __float2bfloat16(v);
        __nv_bfloat16 l = __float2bfloat16(v - __bfloat162float(h));
        size_t o = (((size_t)(b * 9 + uv) * 128) + f) * 128 + sblk * 8 + sl;
        g_W2hi[o] = h;
        g_W2lo[o] = l;
    }
}

// ===========================================================================
// Kernel X: x -> padded channel-last split-bf16 (b, row 34, col 36, s 128)
// ===========================================================================
__global__ __launch_bounds__(256) void xprep_kernel(const float* __restrict__ x)
{
    __shared__ float sX[128 * 33];
    const int b = blockIdx.y, p = blockIdx.x, tid = threadIdx.x;
    for (int i = tid; i < 4096; i += 256) {
        int s = i >> 5, q = i & 31;
        sX[s * 33 + q] = x[(((size_t)(b * 128 + s)) * 32 + p) * 32 + q];
    }
    __syncthreads();
    for (int i = tid; i < 4096; i += 256) {
        int s = i & 127, q = i >> 7;
        float v = sX[s * 33 + q];
        __nv_bfloat16 h = __float2bfloat16(v);
        __nv_bfloat16 l = __float2bfloat16(v - __bfloat162float(h));
        size_t o = (((size_t)b * 34 + (p + 1)) * 36 + (q + 1)) * 128 + s;
        g_xhi[o] = h;
        g_xlo[o] = l;
    }
}

// ===========================================================================
// Kernel C: per-sample conv as split-bf16 HMMA GEMM (unchanged, proven R4).
// ===========================================================================
#define APITCH 144           // 64 bf16 + 8 pad
#define BUFSZ  110592
#define CSMEM  221184

__global__ __launch_bounds__(512, 1) void conv_mma_kernel(
    const float* __restrict__ xin,
    const float* __restrict__ bias,
    float* __restrict__ out)
{
    extern __shared__ char smem[];
    const uint32_t sb = smem_u32(smem);
    const int tid = threadIdx.x, wid = tid >> 5, lane = tid & 31;
    const int b = blockIdx.y, pb = blockIdx.x;
    const int f0 = (wid >> 2) * 32;
    const int px0 = (wid & 3) * 64;

    float d[2][8][4];
#pragma unroll
    for (int i = 0; i < 2; i++)
#pragma unroll
        for (int j = 0; j < 8; j++)
#pragma unroll
            for (int e = 0; e < 4; e++) d[i][j][e] = 0.0f;

    const uint32_t aoff = (uint32_t)((lane & 15) * APITCH + (lane >> 4) * 16);
    const uint32_t boff = (uint32_t)(((lane & 7) + ((lane >> 4) << 3)) * APITCH + ((lane >> 3) & 1) * 16);

    auto issue_stage = [&](int st) {
        const int uv = st >> 1, c = st & 1;
        const int u = uv / 3, v = uv - 3 * u;
        const uint32_t base = sb + (uint32_t)(st & 1) * BUFSZ;
#pragma unroll
        for (int i = 0; i < 4; i++) {
            int c2 = i * 512 + tid;
            int half = c2 >> 10, rem = c2 & 1023, row = rem >> 3, seg = rem & 7;
            const __nv_bfloat16* src =
                (half ? g_W2lo : g_W2hi) +
                (((size_t)(b * 9 + uv) * 128 + row) * 128 + c * 64 + seg * 8);
            cp16(base + half * 18432 + row * APITCH + seg * 16, src);
        }
#pragma unroll
        for (int i = 0; i < 8; i++) {
            int c2 = i * 512 + tid;
            int half = c2 >> 11, rem = c2 & 2047, px = rem >> 3, seg = rem & 7;
            int prow = pb * 8 + (px >> 5), pcol = px & 31;
            const __nv_bfloat16* src =
                (half ? g_xlo : g_xhi) +
                (((size_t)(b * 34 + prow + u) * 36 + (pcol + v)) * 128 + c * 64 + seg * 8);
            cp16(base + 36864 + half * 36864 + px * APITCH + seg * 16, src);
        }
        CP_COMMIT();
    };

    issue_stage(0);
    issue_stage(1);

    for (int st = 0; st < 18; st++) {
        if (st < 17) asm volatile("cp.async.wait_group 1;" ::: "memory");
        else         asm volatile("cp.async.wait_group 0;" ::: "memory");
        __syncthreads();

        const uint32_t base = sb + (uint32_t)(st & 1) * BUFSZ;
        const uint32_t baseAh = base, baseAl = base + 18432;
        const uint32_t baseBh = base + 36864, baseBl = base + 73728;

#pragma unroll
        for (int kk = 0; kk < 4; kk++) {
            const uint32_t ko = (uint32_t)kk * 32;
            uint32_t ah[2][4], al[2][4], bf[4][4];
#pragma unroll
            for (int i = 0; i < 2; i++) {
                ldsm4(ah[i], baseAh + (f0 + i * 16) * APITCH + ko + aoff);
                ldsm4(al[i], baseAl + (f0 + i * 16) * APITCH + ko + aoff);
            }
#pragma unroll
            for (int p = 0; p < 4; p++)
                ldsm4(bf[p], baseBh + (px0 + p * 16) * APITCH + ko + boff);
#pragma unroll
            for (int i = 0; i < 2; i++)
#pragma unroll
                for (int t = 0; t < 8; t++)
                    mma16816(d[i][t], ah[i], &bf[t >> 1][(t & 1) * 2]);
#pragma unroll
            for (int i = 0; i < 2; i++)
#pragma unroll
                for (int t = 0; t < 8; t++)
                    mma16816(d[i][t], al[i], &bf[t >> 1][(t & 1) * 2]);
#pragma unroll
            for (int p = 0; p < 4; p++)
                ldsm4(bf[p], baseBl + (px0 + p * 16) * APITCH + ko + boff);
#pragma unroll
            for (int i = 0; i < 2; i++)
#pragma unroll
                for (int t = 0; t < 8; t++)
                    mma16816(d[i][t], ah[i], &bf[t >> 1][(t & 1) * 2]);
        }
        __syncthreads();
        if (st + 2 < 18) issue_stage(st + 2);
    }

    const int g = lane >> 2, tc = lane & 3;
#pragma unroll
    for (int i = 0; i < 2; i++) {
        const int fr0 = f0 + i * 16 + g;
        const float bv0 = __ldg(&bias[fr0]);
        const float bv1 = __ldg(&bias[fr0 + 8]);
#pragma unroll
        for (int j = 0; j < 8; j++) {
            const int pix = pb * 256 + px0 + j * 8 + tc * 2;
            {
                size_t o = ((size_t)(b * 128 + fr0)) * 1024 + pix;
                float2 xr = *reinterpret_cast<const float2*>(xin + o);
                float2 w = make_float2(d[i][j][0] + xr.x + bv0,
                                       d[i][j][1] + xr.y + bv0);
                *reinterpret_cast<float2*>(out + o) = w;
            }
            {
                size_t o = ((size_t)(b * 128 + fr0 + 8)) * 1024 + pix;
                float2 xr = *reinterpret_cast<const float2*>(xin + o);
                float2 w = make_float2(d[i][j][2] + xr.x + bv1,
                                       d[i][j][3] + xr.y + bv1);
                *reinterpret_cast<float2*>(out + o) = w;
            }
        }
    }
}

// ===========================================================================
extern "C" void kernel_launch(void* const* d_in, const int* in_sizes, int n_in,
                              void* d_out, int out_size)
{
    (void)in_sizes; (void)n_in; (void)out_size;
    const float* x     = (const float*)d_in[0];
    const float* z     = (const float*)d_in[1];
    const float* dw    = (const float*)d_in[2];
    const float* db    = (const float*)d_in[3];
    const float* gamma = (const float*)d_in[4];
    const float* beta  = (const float*)d_in[5];
    const float* bconv = (const float*)d_in[6];
    float* out = (float*)d_out;

    cudaFuncSetAttribute(hyper_mma_kernel,
                         cudaFuncAttributeMaxDynamicSharedMemorySize, HP_SMEM);
    cudaFuncSetAttribute(conv_mma_kernel,
                         cudaFuncAttributeMaxDynamicSharedMemorySize, CSMEM);

    hyper_mma_kernel<<<NB / 256, 512, HP_SMEM>>>(z, dw, db, gamma, beta);
    xprep_kernel<<<dim3(32, BATCH), 256>>>(x);
    wtrans_kernel<<<dim3(16, BATCH), 256>>>();
    conv_mma_kernel<<<dim3(4, BATCH), 512, CSMEM>>>(x, bconv, out);
}